// round 2
// baseline (speedup 1.0000x reference)
#include <cuda_runtime.h>
#include <cuda_bf16.h>

// Problem constants (fixed shapes for this dataset)
#define M_ROWS   2048
#define N_LAT    8192
#define DIM      256
#define ROWS_CTA 16
#define LAT_SLICE 1024
#define LAT_CHUNK 256
#define DCHUNK   16
#define NSTAGE   (DIM / DCHUNK)          // 16
#define NCHUNK   (LAT_SLICE / LAT_CHUNK) // 4
#define NSLICE   (N_LAT / LAT_SLICE)     // 8
#define NDP      (DCHUNK / 2)            // 8 d-pairs per stage

typedef unsigned long long ull;

__device__ float g_cand[M_ROWS * NSLICE * 4];
__device__ float g_tail[M_ROWS];

static __device__ __forceinline__ ull pk(float a, float b) {
    return (ull)__float_as_uint(a) | ((ull)__float_as_uint(b) << 32);
}

// packed |lat + (-row)| accumulate:  A += abs2(R + L)   (R holds negated rows)
#define ABSACC(A, R, L) do {                                        \
    ull _d;                                                         \
    asm("add.rn.f32x2 %0, %1, %2;" : "=l"(_d) : "l"(R), "l"(L));    \
    _d &= 0x7fffffff7fffffffULL;                                    \
    asm("add.rn.f32x2 %0, %1, %2;" : "=l"(A) : "l"(A), "l"(_d));    \
} while (0)

#define CP_ASYNC8(dst_u32, src_ptr) \
    asm volatile("cp.async.ca.shared.global [%0], [%1], 8;" :: "r"(dst_u32), "l"(src_ptr))
#define CP_COMMIT()  asm volatile("cp.async.commit_group;" ::: "memory")
#define CP_WAIT0()   asm volatile("cp.async.wait_group 0;" ::: "memory")

static __device__ __forceinline__ void ins4(float v, float& m0, float& m1, float& m2, float& m3) {
    if (v < m3) {
        float c2 = fminf(v,  m2), d3 = fmaxf(v,  m2);
        float c1 = fminf(c2, m1), d2 = fmaxf(c2, m1);
        float c0 = fminf(c1, m0), d1 = fmaxf(c1, m0);
        m0 = c0; m1 = d1; m2 = d2; m3 = d3;
    }
}

static __device__ __forceinline__ float huber1(float x) {
    return (x < 1.0f) ? (0.5f * x * x) : (x - 0.5f);
}

// ---------------------------------------------------------------------------
// Kernel 1: L1 cdist + per-(row, slice) smallest-4 candidates
// grid (128, 8), block 256, 3 CTAs/SM
// ---------------------------------------------------------------------------
__global__ void __launch_bounds__(256, 3)
k1_cdist_min4(const float* __restrict__ space, const float* __restrict__ lat) {
    __shared__ ull rowS[(DIM / 2) * ROWS_CTA];   // [128 dpairs][16 rows]  16KB (negated)
    __shared__ ull latS[2][NDP][LAT_CHUNK];      // double-buffered        32KB

    const int tid = threadIdx.x;
    const int rowBase = blockIdx.x * ROWS_CTA;
    const int slice = blockIdx.y;
    const int r0 = (tid >> 6) * 4;     // 0,4,8,12
    const int c0 = tid & 63;           // this thread owns latents 4*c0 .. 4*c0+3

    // ---- stage rows once (negated, d-pair major) ----
    {
        const float* srow = space + rowBase * DIM;
        #pragma unroll
        for (int k = 0; k < 4; ++k) {
            int f4 = tid + k * 256;
            int r  = f4 >> 6;
            int dd = (f4 & 63) << 2;
            float4 v = *reinterpret_cast<const float4*>(srow + r * DIM + dd);
            rowS[(dd >> 1) * ROWS_CTA + r]       = pk(-v.x, -v.y);
            rowS[((dd >> 1) + 1) * ROWS_CTA + r] = pk(-v.z, -v.w);
        }
    }

    float m[4][4];
    #pragma unroll
    for (int i = 0; i < 4; ++i)
        #pragma unroll
        for (int k = 0; k < 4; ++k) m[i][k] = 1e30f;

    for (int chunk = 0; chunk < NCHUNK; ++chunk) {
        const int nb = slice * LAT_SLICE + chunk * LAT_CHUNK;
        const float* lsrc = lat + (size_t)(nb + tid) * DIM;  // this thread stages latent `tid`

        // prologue: stage 0 -> buf 0  (safe: buf0 last read two stages back)
        {
            unsigned d0 = (unsigned)__cvta_generic_to_shared(&latS[0][0][tid]);
            #pragma unroll
            for (int k = 0; k < NDP; ++k)
                CP_ASYNC8(d0 + (unsigned)(k * LAT_CHUNK * 8), lsrc + 2 * k);
            CP_COMMIT();
        }

        ull acc[4][4];
        #pragma unroll
        for (int i = 0; i < 4; ++i)
            #pragma unroll
            for (int j = 0; j < 4; ++j) acc[i][j] = 0ULL;

        for (int s = 0; s < NSTAGE; ++s) {
            CP_WAIT0();
            __syncthreads();   // stage s data visible; everyone done reading buf[(s+1)&1]

            if (s + 1 < NSTAGE) {
                unsigned dn = (unsigned)__cvta_generic_to_shared(&latS[(s + 1) & 1][0][tid]);
                const float* sp = lsrc + (s + 1) * DCHUNK;
                #pragma unroll
                for (int k = 0; k < NDP; ++k)
                    CP_ASYNC8(dn + (unsigned)(k * LAT_CHUNK * 8), sp + 2 * k);
                CP_COMMIT();
            }

            const ull* bufp = &latS[s & 1][0][0];
            #pragma unroll
            for (int dp = 0; dp < NDP; ++dp) {
                const ull* rp = rowS + (s * NDP + dp) * ROWS_CTA + r0;
                ulonglong2 ra = *reinterpret_cast<const ulonglong2*>(rp);
                ulonglong2 rb = *reinterpret_cast<const ulonglong2*>(rp + 2);
                ull rv0 = ra.x, rv1 = ra.y, rv2 = rb.x, rv3 = rb.y;
                const ull* cp = bufp + dp * LAT_CHUNK + 4 * c0;
                ulonglong2 la = *reinterpret_cast<const ulonglong2*>(cp);
                ulonglong2 lb = *reinterpret_cast<const ulonglong2*>(cp + 2);
                ull lv0 = la.x, lv1 = la.y, lv2 = lb.x, lv3 = lb.y;

                ABSACC(acc[0][0], rv0, lv0); ABSACC(acc[0][1], rv0, lv1);
                ABSACC(acc[0][2], rv0, lv2); ABSACC(acc[0][3], rv0, lv3);
                ABSACC(acc[1][0], rv1, lv0); ABSACC(acc[1][1], rv1, lv1);
                ABSACC(acc[1][2], rv1, lv2); ABSACC(acc[1][3], rv1, lv3);
                ABSACC(acc[2][0], rv2, lv0); ABSACC(acc[2][1], rv2, lv1);
                ABSACC(acc[2][2], rv2, lv2); ABSACC(acc[2][3], rv2, lv3);
                ABSACC(acc[3][0], rv3, lv0); ABSACC(acc[3][1], rv3, lv1);
                ABSACC(acc[3][2], rv3, lv2); ABSACC(acc[3][3], rv3, lv3);
            }
        }

        #pragma unroll
        for (int i = 0; i < 4; ++i) {
            #pragma unroll
            for (int j = 0; j < 4; ++j) {
                float lo = __uint_as_float((unsigned)(acc[i][j] & 0xffffffffULL));
                float hi = __uint_as_float((unsigned)(acc[i][j] >> 32));
                ins4(lo + hi, m[i][0], m[i][1], m[i][2], m[i][3]);
            }
        }
    }

    // ---- CTA merge: each row's 64*4 candidates -> top-4 ----
    __syncthreads();
    float* mb = reinterpret_cast<float*>(&latS[0][0][0]);  // 16KB reuse
    #pragma unroll
    for (int i = 0; i < 4; ++i)
        #pragma unroll
        for (int k = 0; k < 4; ++k)
            mb[(r0 + i) * 256 + c0 * 4 + k] = m[i][k];
    __syncthreads();

    if (tid < ROWS_CTA) {
        float t0 = 1e30f, t1 = 1e30f, t2 = 1e30f, t3 = 1e30f;
        const float* p = mb + tid * 256;
        for (int q = 0; q < 256; ++q) ins4(p[q], t0, t1, t2, t3);
        float* dst = g_cand + ((size_t)(rowBase + tid) * NSLICE + slice) * 4;
        dst[0] = t0; dst[1] = t1; dst[2] = t2; dst[3] = t3;
    }
}

// ---------------------------------------------------------------------------
__global__ void k2_merge_tail() {
    int idx = blockIdx.x * blockDim.x + threadIdx.x;
    if (idx >= M_ROWS) return;
    const float* p = g_cand + (size_t)idx * NSLICE * 4;
    float m0 = 1e30f, m1 = 1e30f, m2 = 1e30f, m3 = 1e30f;
    #pragma unroll
    for (int q = 0; q < NSLICE * 4; ++q) ins4(p[q], m0, m1, m2, m3);
    g_tail[idx] = (m0 + m1 + m2 + m3) * 0.25f;
}

// ---------------------------------------------------------------------------
// Kernel 3: top-64 largest of tail[2048] via bit binary search, huber mean
// ---------------------------------------------------------------------------
__global__ void k3_top64_huber(float* __restrict__ out) {
    __shared__ int   wred[8];
    __shared__ float wfred[8];
    __shared__ unsigned s_lo, s_hi;
    const int t = threadIdx.x;

    unsigned b[8];
    #pragma unroll
    for (int k = 0; k < 8; ++k) b[k] = __float_as_uint(g_tail[t + 256 * k]);

    if (t == 0) { s_lo = 0u; s_hi = 0x7f800000u; }
    __syncthreads();
    unsigned lo = s_lo, hi = s_hi;

    while (hi - lo > 1u) {
        unsigned mid = lo + ((hi - lo) >> 1);
        int c = 0;
        #pragma unroll
        for (int k = 0; k < 8; ++k) c += (b[k] >= mid);
        #pragma unroll
        for (int o = 16; o; o >>= 1) c += __shfl_down_sync(0xffffffffu, c, o);
        if ((t & 31) == 0) wred[t >> 5] = c;
        __syncthreads();
        if (t == 0) {
            int tot = 0;
            #pragma unroll
            for (int w = 0; w < 8; ++w) tot += wred[w];
            if (tot >= 64) s_lo = mid; else s_hi = mid;
        }
        __syncthreads();
        lo = s_lo; hi = s_hi;
        __syncthreads();
    }

    int c = 0; float hs = 0.0f;
    #pragma unroll
    for (int k = 0; k < 8; ++k) {
        if (b[k] > lo) { ++c; hs += huber1(__uint_as_float(b[k])); }
    }
    #pragma unroll
    for (int o = 16; o; o >>= 1) {
        c  += __shfl_down_sync(0xffffffffu, c, o);
        hs += __shfl_down_sync(0xffffffffu, hs, o);
    }
    if ((t & 31) == 0) { wred[t >> 5] = c; wfred[t >> 5] = hs; }
    __syncthreads();
    if (t == 0) {
        int ngt = 0; float tot = 0.0f;
        #pragma unroll
        for (int w = 0; w < 8; ++w) { ngt += wred[w]; tot += wfred[w]; }
        float tv = __uint_as_float(lo);
        out[0] = (tot + (float)(64 - ngt) * huber1(tv)) * (1.0f / 64.0f);
    }
}

// ---------------------------------------------------------------------------
extern "C" void kernel_launch(void* const* d_in, const int* in_sizes, int n_in,
                              void* d_out, int out_size) {
    const float* a = (const float*)d_in[0];
    const float* b = (const float*)d_in[1];
    const float *space, *lats;
    if (in_sizes[0] == M_ROWS * DIM) { space = a; lats = b; }
    else                             { space = b; lats = a; }

    dim3 g1(M_ROWS / ROWS_CTA, NSLICE);
    k1_cdist_min4<<<g1, 256>>>(space, lats);
    k2_merge_tail<<<(M_ROWS + 255) / 256, 256>>>();
    k3_top64_huber<<<1, 256>>>((float*)d_out);
}

// round 4
// speedup vs baseline: 1.6392x; 1.6392x over previous
#include <cuda_runtime.h>
#include <cuda_bf16.h>

// Fixed shapes
#define M_ROWS   2048
#define N_LAT    8192
#define DIM      256
#define ROWS_CTA 32
#define LATS_CTA 256
#define NRB      (M_ROWS / ROWS_CTA)   // 64
#define NLB      (N_LAT / LATS_CTA)    // 32
#define NQ_TOT   (DIM / 4)             // 64 quads of 4 floats
#define NSTAGE   32                    // stages of 8 floats (2 quads)
#define QPS      2

typedef unsigned long long ull;

__device__ float g_cand[M_ROWS * NLB * 4];
__device__ float g_tail[M_ROWS];

// A += |R + L|  (packed f32x2; R holds negated row values)
#define ABSACC(A, R, L) do { ull _d;                                \
    asm("add.rn.f32x2 %0, %1, %2;" : "=l"(_d) : "l"(R), "l"(L));    \
    _d &= 0x7fffffff7fffffffULL;                                    \
    asm("add.rn.f32x2 %0, %1, %2;" : "=l"(A) : "l"(A), "l"(_d));    \
} while (0)

#define CP16(dst_u32, src_ptr) \
    asm volatile("cp.async.cg.shared.global [%0], [%1], 16;" :: "r"(dst_u32), "l"(src_ptr))
#define CP_COMMIT()  asm volatile("cp.async.commit_group;" ::: "memory")
#define CP_WAIT0()   asm volatile("cp.async.wait_group 0;" ::: "memory")

static __device__ __forceinline__ void ins4(float v, float& m0, float& m1, float& m2, float& m3) {
    if (v < m3) {
        float c2 = fminf(v,  m2), d3 = fmaxf(v,  m2);
        float c1 = fminf(c2, m1), d2 = fmaxf(c2, m1);
        float c0 = fminf(c1, m0), d1 = fmaxf(c1, m0);
        m0 = c0; m1 = d1; m2 = d2; m3 = d3;
    }
}

static __device__ __forceinline__ float huber1(float x) {
    return (x < 1.0f) ? (0.5f * x * x) : (x - 0.5f);
}

// ---------------------------------------------------------------------------
// Kernel 1: L1 cdist over a 32-row x 256-latent tile; min-4 per (row, latblock)
// grid (64, 32), block 256, 2 CTAs/SM
// ---------------------------------------------------------------------------
__global__ void __launch_bounds__(256, 2)
k1_cdist_min4(const float* __restrict__ space, const float* __restrict__ lat) {
    __shared__ float4 rowS[NQ_TOT][ROWS_CTA];   // 32KB persistent (negated rows)
    __shared__ float4 latS[2][QPS][LATS_CTA];   // 16KB double-buffered

    const int tid = threadIdx.x;
    const int rowBase = blockIdx.x * ROWS_CTA;
    const int latBase = blockIdx.y * LATS_CTA;
    const int r0 = (tid >> 6) * 8;     // warp-uniform: 0,8,16,24
    const int c0 = tid & 63;           // lats c0, c0+64, c0+128, c0+192

    // ---- stage rows negated: unit u -> row u&31, quad u>>5 (conflict-free) ----
    #pragma unroll
    for (int k = 0; k < 8; ++k) {
        int u = tid + k * 256;
        int r = u & 31, q = u >> 5;
        float4 v = reinterpret_cast<const float4*>(space + (size_t)(rowBase + r) * DIM)[q];
        rowS[q][r] = make_float4(-v.x, -v.y, -v.z, -v.w);
    }

    const float* lsrc = lat + (size_t)(latBase + tid) * DIM;  // thread stages latent `tid`

    {   // prologue: stage 0 -> buf 0
        unsigned d0 = (unsigned)__cvta_generic_to_shared(&latS[0][0][tid]);
        unsigned d1 = (unsigned)__cvta_generic_to_shared(&latS[0][1][tid]);
        CP16(d0, lsrc);
        CP16(d1, lsrc + 4);
        CP_COMMIT();
    }

    ull acc[8][4];
    #pragma unroll
    for (int i = 0; i < 8; ++i)
        #pragma unroll
        for (int j = 0; j < 4; ++j) acc[i][j] = 0ULL;

    for (int s = 0; s < NSTAGE; ++s) {
        CP_WAIT0();
        __syncthreads();   // stage-s latents visible; rowS staged (s==0); prev buf free

        if (s + 1 < NSTAGE) {
            const float* sp = lsrc + (s + 1) * 8;
            unsigned d0 = (unsigned)__cvta_generic_to_shared(&latS[(s + 1) & 1][0][tid]);
            unsigned d1 = (unsigned)__cvta_generic_to_shared(&latS[(s + 1) & 1][1][tid]);
            CP16(d0, sp);
            CP16(d1, sp + 4);
            CP_COMMIT();
        }

        #pragma unroll
        for (int q = 0; q < QPS; ++q) {
            const float4* lb = &latS[s & 1][q][0];
            ulonglong2 lv0 = *reinterpret_cast<const ulonglong2*>(lb + c0);
            ulonglong2 lv1 = *reinterpret_cast<const ulonglong2*>(lb + c0 + 64);
            ulonglong2 lv2 = *reinterpret_cast<const ulonglong2*>(lb + c0 + 128);
            ulonglong2 lv3 = *reinterpret_cast<const ulonglong2*>(lb + c0 + 192);
            const float4* rb = &rowS[2 * s + q][r0];
            #pragma unroll
            for (int ri = 0; ri < 8; ++ri) {
                ulonglong2 rv = *reinterpret_cast<const ulonglong2*>(rb + ri);
                ABSACC(acc[ri][0], rv.x, lv0.x); ABSACC(acc[ri][0], rv.y, lv0.y);
                ABSACC(acc[ri][1], rv.x, lv1.x); ABSACC(acc[ri][1], rv.y, lv1.y);
                ABSACC(acc[ri][2], rv.x, lv2.x); ABSACC(acc[ri][2], rv.y, lv2.y);
                ABSACC(acc[ri][3], rv.x, lv3.x); ABSACC(acc[ri][3], rv.y, lv3.y);
            }
        }
    }

    // ---- epilogue: fold packed halves -> dist matrix in smem ----
    __syncthreads();   // everyone done reading rowS
    float* db = reinterpret_cast<float*>(&rowS[0][0]);   // [32][256] floats
    #pragma unroll
    for (int ri = 0; ri < 8; ++ri) {
        float* drow = db + (r0 + ri) * LATS_CTA;
        #pragma unroll
        for (int j = 0; j < 4; ++j) {
            float lo = __uint_as_float((unsigned)(acc[ri][j] & 0xffffffffULL));
            float hi = __uint_as_float((unsigned)(acc[ri][j] >> 32));
            drow[c0 + 64 * j] = lo + hi;
        }
    }
    __syncthreads();

    // stage-1 reduce: thread -> row tid>>3, 32-float segment (tid&7), staggered
    {
        int row = tid >> 3;
        int seg = (tid & 7) * 32;
        const float* p = db + row * LATS_CTA;
        float m0 = 1e30f, m1 = 1e30f, m2 = 1e30f, m3 = 1e30f;
        #pragma unroll 8
        for (int q = 0; q < 32; ++q)
            ins4(p[seg + ((q + tid) & 31)], m0, m1, m2, m3);
        float4* c4 = reinterpret_cast<float4*>(&latS[0][0][0]);   // [32][8] float4
        c4[row * 8 + (tid & 7)] = make_float4(m0, m1, m2, m3);
    }
    __syncthreads();

    if (tid < ROWS_CTA) {
        const float* cf = reinterpret_cast<const float*>(&latS[0][0][0]) + tid * 32;
        float m0 = 1e30f, m1 = 1e30f, m2 = 1e30f, m3 = 1e30f;
        #pragma unroll 8
        for (int k = 0; k < 32; ++k)
            ins4(cf[(k + tid) & 31], m0, m1, m2, m3);
        float4* dst = reinterpret_cast<float4*>(
            g_cand + ((size_t)(rowBase + tid) * NLB + blockIdx.y) * 4);
        *dst = make_float4(m0, m1, m2, m3);
    }
}

// ---------------------------------------------------------------------------
__global__ void k2_merge_tail() {
    int idx = blockIdx.x * blockDim.x + threadIdx.x;
    if (idx >= M_ROWS) return;
    const float* p = g_cand + (size_t)idx * NLB * 4;
    float m0 = 1e30f, m1 = 1e30f, m2 = 1e30f, m3 = 1e30f;
    #pragma unroll 4
    for (int q = 0; q < NLB * 4; ++q) ins4(p[q], m0, m1, m2, m3);
    g_tail[idx] = (m0 + m1 + m2 + m3) * 0.25f;
}

// ---------------------------------------------------------------------------
// Kernel 3: top-64 largest of tail[2048] via bit binary search, huber mean
// ---------------------------------------------------------------------------
__global__ void k3_top64_huber(float* __restrict__ out) {
    __shared__ int   wred[8];
    __shared__ float wfred[8];
    __shared__ unsigned s_lo, s_hi;
    const int t = threadIdx.x;

    unsigned b[8];
    #pragma unroll
    for (int k = 0; k < 8; ++k) b[k] = __float_as_uint(g_tail[t + 256 * k]);

    if (t == 0) { s_lo = 0u; s_hi = 0x7f800000u; }
    __syncthreads();
    unsigned lo = s_lo, hi = s_hi;

    while (hi - lo > 1u) {
        unsigned mid = lo + ((hi - lo) >> 1);
        int c = 0;
        #pragma unroll
        for (int k = 0; k < 8; ++k) c += (b[k] >= mid);
        #pragma unroll
        for (int o = 16; o; o >>= 1) c += __shfl_down_sync(0xffffffffu, c, o);
        if ((t & 31) == 0) wred[t >> 5] = c;
        __syncthreads();
        if (t == 0) {
            int tot = 0;
            #pragma unroll
            for (int w = 0; w < 8; ++w) tot += wred[w];
            if (tot >= 64) s_lo = mid; else s_hi = mid;
        }
        __syncthreads();
        lo = s_lo; hi = s_hi;
        __syncthreads();
    }

    int c = 0; float hs = 0.0f;
    #pragma unroll
    for (int k = 0; k < 8; ++k)
        if (b[k] > lo) { ++c; hs += huber1(__uint_as_float(b[k])); }
    #pragma unroll
    for (int o = 16; o; o >>= 1) {
        c  += __shfl_down_sync(0xffffffffu, c, o);
        hs += __shfl_down_sync(0xffffffffu, hs, o);
    }
    if ((t & 31) == 0) { wred[t >> 5] = c; wfred[t >> 5] = hs; }
    __syncthreads();
    if (t == 0) {
        int ngt = 0; float tot = 0.0f;
        #pragma unroll
        for (int w = 0; w < 8; ++w) { ngt += wred[w]; tot += wfred[w]; }
        float tv = __uint_as_float(lo);
        out[0] = (tot + (float)(64 - ngt) * huber1(tv)) * (1.0f / 64.0f);
    }
}

// ---------------------------------------------------------------------------
extern "C" void kernel_launch(void* const* d_in, const int* in_sizes, int n_in,
                              void* d_out, int out_size) {
    const float* a = (const float*)d_in[0];
    const float* b = (const float*)d_in[1];
    const float *space, *lats;
    if (in_sizes[0] == M_ROWS * DIM) { space = a; lats = b; }
    else                             { space = b; lats = a; }

    dim3 g1(NRB, NLB);   // 64 x 32
    k1_cdist_min4<<<g1, 256>>>(space, lats);
    k2_merge_tail<<<(M_ROWS + 255) / 256, 256>>>();
    k3_top64_huber<<<1, 256>>>((float*)d_out);
}